// round 4
// baseline (speedup 1.0000x reference)
#include <cuda_runtime.h>

#define NN 50000
#define FF 64
#define EE 800000
#define BCAP 128          // per-row bucket capacity (Poisson(16) tail @128 ~ 1e-60)

// Scratch (static __device__ — zero-initialized at module load; edge kernel
// resets g_cnt so every graph replay starts from zeros)
__device__ float g_q[(size_t)NN * 128];         // [N][h*64+f]
__device__ float g_k[(size_t)NN * 128];
__device__ int   g_cnt[NN];
__device__ int2  g_bucket[(size_t)NN * BCAP];   // (col, orig edge id)

// f32x2 packed-math helpers (Blackwell FFMA2 path — only reachable via PTX)
#define FMA_F32X2(d, a, b, c) \
    asm("fma.rn.f32x2 %0, %1, %2, %3;" : "=l"(d) : "l"(a), "l"(b), "l"(c))
#define ADD_F32X2(d, a, b) \
    asm("add.rn.f32x2 %0, %1, %2;" : "=l"(d) : "l"(a), "l"(b))
#define PACK_F32X2(d, lo, hi) \
    asm("mov.b64 %0, {%1, %2};" : "=l"(d) : "f"(lo), "f"(hi))
#define UNPACK_F32X2(lo, hi, s) \
    asm("mov.b64 {%0, %1}, %2;" : "=f"(lo), "=f"(hi) : "l"(s))

// ---------------- direct bucketing (replaces hist+scan+scatter) ----------------
// 4 edges per thread: 4 independent atomic chains hide ATOMG latency.
__global__ void __launch_bounds__(256) bucket_kernel(const int4* __restrict__ row4,
                                                     const int4* __restrict__ col4) {
    int i = blockIdx.x * blockDim.x + threadIdx.x;
    if (i >= EE / 4) return;
    int4 r = __ldg(row4 + i);
    int4 c = __ldg(col4 + i);
    int e = i * 4;
    int p0 = atomicAdd(&g_cnt[r.x], 1);
    int p1 = atomicAdd(&g_cnt[r.y], 1);
    int p2 = atomicAdd(&g_cnt[r.z], 1);
    int p3 = atomicAdd(&g_cnt[r.w], 1);
    if (p0 < BCAP) g_bucket[(size_t)r.x * BCAP + p0] = make_int2(c.x, e + 0);
    if (p1 < BCAP) g_bucket[(size_t)r.y * BCAP + p1] = make_int2(c.y, e + 1);
    if (p2 < BCAP) g_bucket[(size_t)r.z * BCAP + p2] = make_int2(c.z, e + 2);
    if (p3 < BCAP) g_bucket[(size_t)r.w * BCAP + p3] = make_int2(c.w, e + 3);
}

// ---------------- QK projection GEMM (f32x2 / FFMA2) ----------------
__global__ void __launch_bounds__(256, 1) gemm_qk_kernel(const float* __restrict__ x,
                                                         const float* __restrict__ W,
                                                         const float* __restrict__ b) {
    __shared__ float2 xs[64 * 64];   // [row][k] duplicated (v,v) pairs, 32KB
    const int tid = threadIdx.x;
    const int n0 = blockIdx.x * 64;

#pragma unroll
    for (int i = 0; i < 4; i++) {
        int lin = tid + i * 256;          // float4 index
        int r = lin >> 4, k4 = lin & 15;
        int n = n0 + r;
        float4 v = make_float4(0.f, 0.f, 0.f, 0.f);
        if (n < NN) v = __ldg((const float4*)x + (size_t)n * 16 + k4);
        float2* dst = &xs[r * 64 + k4 * 4];
        dst[0] = make_float2(v.x, v.x);
        dst[1] = make_float2(v.y, v.y);
        dst[2] = make_float2(v.z, v.z);
        dst[3] = make_float2(v.w, v.w);
    }

    const int c = tid & 127;              // column pair (c, c+128): two heads
    const int rbase = (tid >> 7) * 32;

    unsigned long long wp[64];
#pragma unroll
    for (int k = 0; k < 64; k++) {
        float w0 = __ldg(W + k * 256 + c);
        float w1 = __ldg(W + k * 256 + c + 128);
        PACK_F32X2(wp[k], w0, w1);
    }
    const float b0 = __ldg(b + c);
    const float b1 = __ldg(b + c + 128);

    __syncthreads();

    const int sflag = (c >> 6) & 1;       // 0 -> q table, 1 -> k table
    const int f = c & 63;
    float* outbase = sflag ? g_k : g_q;

    for (int r = rbase; r < rbase + 32; r++) {
        int n = n0 + r;
        if (n >= NN) break;
        unsigned long long acc_a, acc_b;
        PACK_F32X2(acc_a, b0, b1);
        PACK_F32X2(acc_b, 0.0f, 0.0f);
        const ulonglong2* xr = (const ulonglong2*)&xs[r * 64];
#pragma unroll
        for (int j = 0; j < 32; j++) {
            ulonglong2 xv = xr[j];
            FMA_F32X2(acc_a, xv.x, wp[2 * j], acc_a);
            FMA_F32X2(acc_b, xv.y, wp[2 * j + 1], acc_b);
        }
        unsigned long long acc;
        ADD_F32X2(acc, acc_a, acc_b);
        float o0, o1;
        UNPACK_F32X2(o0, o1, acc);
        outbase[(size_t)n * 128 + f] = o0;
        outbase[(size_t)n * 128 + 64 + f] = o1;
    }
}

// ---------------- fused edge scores + softmax + output ----------------
// One warp per row. Bucket staged to smem, k-gather 8-wide (MLP=8), remainder
// via index clamp (padded loads hit L1, guarded stores). Resets g_cnt.
__global__ void __launch_bounds__(256) edge_row_kernel(float* __restrict__ out) {
    __shared__ int2   sse[8][BCAP];
    __shared__ float2 exs[8][BCAP];
    const int warp = threadIdx.x >> 5;
    const int lane = threadIdx.x & 31;
    const int r = blockIdx.x * 8 + warp;
    if (r >= NN) return;

    int deg = g_cnt[r];
    if (lane == 0) g_cnt[r] = 0;          // reset for next graph replay
    if (deg == 0) return;
    if (deg > BCAP) deg = BCAP;           // unreachable; safety

    const int2* bucket = g_bucket + (size_t)r * BCAP;
    for (int j = lane; j < deg; j += 32) sse[warp][j] = bucket[j];
    __syncwarp();

    const float4 qv = *(const float4*)(g_q + (size_t)r * 128 + lane * 4);
    const float4* kp = (const float4*)g_k;
    const bool head_lane = ((lane & 15) == 0);
    const int h = lane >> 4;
    float d = 0.0f;

    for (int pos = 0; pos < deg; pos += 8) {
        float4 kv[8];
#pragma unroll
        for (int u = 0; u < 8; u++) {
            int j = pos + u;
            int jj = (j < deg) ? j : (deg - 1);       // clamp: dup load -> L1 hit
            kv[u] = __ldg(kp + sse[warp][jj].x * 32 + lane);
        }
        float p[8];
#pragma unroll
        for (int u = 0; u < 8; u++)
            p[u] = qv.x * kv[u].x + qv.y * kv[u].y + qv.z * kv[u].z + qv.w * kv[u].w;
#pragma unroll
        for (int off = 8; off >= 1; off >>= 1) {
#pragma unroll
            for (int u = 0; u < 8; u++)
                p[u] += __shfl_xor_sync(0xffffffffu, p[u], off);
        }
        if (head_lane) {
#pragma unroll
            for (int u = 0; u < 8; u++) {
                if (pos + u < deg) {
                    float v = __expf(p[u]);
                    ((float*)&exs[warp][pos + u])[h] = v;
                    d += v;
                }
            }
        }
    }

    float D0 = __shfl_sync(0xffffffffu, d, 0);
    float D1 = __shfl_sync(0xffffffffu, d, 16);
    float i0 = 0.5f / D0, i1 = 0.5f / D1;
    __syncwarp();

    for (int j = lane; j < deg; j += 32) {
        float2 e = exs[warp][j];
        out[sse[warp][j].y] = e.x * i0 + e.y * i1;
    }
}

extern "C" void kernel_launch(void* const* d_in, const int* in_sizes, int n_in,
                              void* d_out, int out_size) {
    const float* x    = (const float*)d_in[0];
    const float* W_qk = (const float*)d_in[1];
    const float* b_qk = (const float*)d_in[2];
    const int*   ei   = (const int*)d_in[3];   // [2, E] row-major
    const int* row = ei;
    const int* col = ei + EE;
    float* out = (float*)d_out;

    bucket_kernel<<<(EE / 4 + 255) / 256, 256>>>((const int4*)row, (const int4*)col);
    gemm_qk_kernel<<<(NN + 63) / 64, 256>>>(x, W_qk, b_qk);
    edge_row_kernel<<<(NN + 7) / 8, 256>>>(out);
}

// round 5
// speedup vs baseline: 1.3090x; 1.3090x over previous
#include <cuda_runtime.h>

#define NN 50000
#define FF 64
#define EE 800000
#define SCAN_BLOCKS ((NN + 255) / 256)   // 196
#define EX_CAP 128

// Scratch (static __device__ — zero-initialized at load; scan1 re-zeros g_hist
// each execution so graph replays are deterministic)
__device__ float g_q[(size_t)NN * 128];      // [N][h*64+f]
__device__ float g_k[(size_t)NN * 128];
__device__ int   g_hist[NN];
__device__ int   g_start[NN + 1];
__device__ int   g_bsum[256];
__device__ int   g_cursor[NN];
__device__ int2  g_sedge[EE];                // (col, orig edge id) row-sorted (compact: L2-friendly)
__device__ float g_ex2[(size_t)EE * 2];      // fallback exp storage (deg > EX_CAP)

// f32x2 packed-math helpers (Blackwell FFMA2 path — only reachable via PTX)
#define FMA_F32X2(d, a, b, c) \
    asm("fma.rn.f32x2 %0, %1, %2, %3;" : "=l"(d) : "l"(a), "l"(b), "l"(c))
#define ADD_F32X2(d, a, b) \
    asm("add.rn.f32x2 %0, %1, %2;" : "=l"(d) : "l"(a), "l"(b))
#define PACK_F32X2(d, lo, hi) \
    asm("mov.b64 %0, {%1, %2};" : "=l"(d) : "f"(lo), "f"(hi))
#define UNPACK_F32X2(lo, hi, s) \
    asm("mov.b64 {%0, %1}, %2;" : "=f"(lo), "=f"(hi) : "l"(s))

// ---------------- counting sort of edges by row ----------------

__global__ void hist_kernel(const int4* __restrict__ row4) {
    int i = blockIdx.x * blockDim.x + threadIdx.x;
    if (i < EE / 4) {
        int4 r = __ldg(row4 + i);
        atomicAdd(&g_hist[r.x], 1);   // no return use -> RED
        atomicAdd(&g_hist[r.y], 1);
        atomicAdd(&g_hist[r.z], 1);
        atomicAdd(&g_hist[r.w], 1);
    }
}

// Within-block exclusive scan of hist; also RESETS g_hist for next replay.
__global__ void scan1_kernel() {
    __shared__ int sh[256];
    int t = threadIdx.x;
    int i = blockIdx.x * 256 + t;
    int v = 0;
    if (i < NN) { v = g_hist[i]; g_hist[i] = 0; }
    sh[t] = v;
    __syncthreads();
#pragma unroll
    for (int off = 1; off < 256; off <<= 1) {
        int u = (t >= off) ? sh[t - off] : 0;
        __syncthreads();
        sh[t] += u;
        __syncthreads();
    }
    if (i < NN) g_start[i] = sh[t] - v;
    if (t == 255) g_bsum[blockIdx.x] = sh[t];
}

// Each block tree-reduces its own exclusive prefix over the 196 block sums.
__global__ void scan3b_kernel() {
    __shared__ int sh[256];
    int t = threadIdx.x;
    int bid = blockIdx.x;
    sh[t] = (t < bid && t < SCAN_BLOCKS) ? g_bsum[t] : 0;
    __syncthreads();
#pragma unroll
    for (int off = 128; off >= 1; off >>= 1) {
        if (t < off) sh[t] += sh[t + off];
        __syncthreads();
    }
    int base = sh[0];
    int i = bid * 256 + t;
    if (i < NN) {
        int s = g_start[i] + base;
        g_start[i] = s;
        g_cursor[i] = s;
    }
    if (i == 0) g_start[NN] = EE;
}

// 4 edges per thread: 4 independent ATOMG->STG chains (MLP=4 vs 318-cyc latency).
__global__ void __launch_bounds__(256) scatter_kernel(const int4* __restrict__ row4,
                                                      const int4* __restrict__ col4) {
    int i = blockIdx.x * blockDim.x + threadIdx.x;
    if (i >= EE / 4) return;
    int4 r = __ldg(row4 + i);
    int4 c = __ldg(col4 + i);
    int e = i * 4;
    int p0 = atomicAdd(&g_cursor[r.x], 1);
    int p1 = atomicAdd(&g_cursor[r.y], 1);
    int p2 = atomicAdd(&g_cursor[r.z], 1);
    int p3 = atomicAdd(&g_cursor[r.w], 1);
    g_sedge[p0] = make_int2(c.x, e + 0);
    g_sedge[p1] = make_int2(c.y, e + 1);
    g_sedge[p2] = make_int2(c.z, e + 2);
    g_sedge[p3] = make_int2(c.w, e + 3);
}

// ---------------- QK projection GEMM (f32x2 / FFMA2) ----------------
__global__ void __launch_bounds__(256, 1) gemm_qk_kernel(const float* __restrict__ x,
                                                         const float* __restrict__ W,
                                                         const float* __restrict__ b) {
    __shared__ float2 xs[64 * 64];   // [row][k] duplicated (v,v) pairs, 32KB
    const int tid = threadIdx.x;
    const int n0 = blockIdx.x * 64;

#pragma unroll
    for (int i = 0; i < 4; i++) {
        int lin = tid + i * 256;          // float4 index
        int r = lin >> 4, k4 = lin & 15;
        int n = n0 + r;
        float4 v = make_float4(0.f, 0.f, 0.f, 0.f);
        if (n < NN) v = __ldg((const float4*)x + (size_t)n * 16 + k4);
        float2* dst = &xs[r * 64 + k4 * 4];
        dst[0] = make_float2(v.x, v.x);
        dst[1] = make_float2(v.y, v.y);
        dst[2] = make_float2(v.z, v.z);
        dst[3] = make_float2(v.w, v.w);
    }

    const int c = tid & 127;              // column pair (c, c+128): two heads
    const int rbase = (tid >> 7) * 32;

    unsigned long long wp[64];
#pragma unroll
    for (int k = 0; k < 64; k++) {
        float w0 = __ldg(W + k * 256 + c);
        float w1 = __ldg(W + k * 256 + c + 128);
        PACK_F32X2(wp[k], w0, w1);
    }
    const float b0 = __ldg(b + c);
    const float b1 = __ldg(b + c + 128);

    __syncthreads();

    const int sflag = (c >> 6) & 1;       // 0 -> q table, 1 -> k table
    const int f = c & 63;
    float* outbase = sflag ? g_k : g_q;

    for (int r = rbase; r < rbase + 32; r++) {
        int n = n0 + r;
        if (n >= NN) break;
        unsigned long long acc_a, acc_b;
        PACK_F32X2(acc_a, b0, b1);
        PACK_F32X2(acc_b, 0.0f, 0.0f);
        const ulonglong2* xr = (const ulonglong2*)&xs[r * 64];
#pragma unroll
        for (int j = 0; j < 32; j++) {
            ulonglong2 xv = xr[j];
            FMA_F32X2(acc_a, xv.x, wp[2 * j], acc_a);
            FMA_F32X2(acc_b, xv.y, wp[2 * j + 1], acc_b);
        }
        unsigned long long acc;
        ADD_F32X2(acc, acc_a, acc_b);
        float o0, o1;
        UNPACK_F32X2(o0, o1, acc);
        outbase[(size_t)n * 128 + f] = o0;
        outbase[(size_t)n * 128 + 64 + f] = o1;
    }
}

// ---------------- fused edge scores + softmax + output (R3-proven) ----------------
__global__ void __launch_bounds__(256) edge_row_kernel(float* __restrict__ out) {
    __shared__ float2 exs[8][EX_CAP + 4];
    const int warp = threadIdx.x >> 5;
    const int lane = threadIdx.x & 31;
    const int r = blockIdx.x * 8 + warp;
    if (r >= NN) return;

    const int s0 = g_start[r];
    const int s1 = g_start[r + 1];
    const int deg = s1 - s0;
    if (deg == 0) return;

    const float4 qv = *(const float4*)(g_q + (size_t)r * 128 + lane * 4);
    const float4* kp = (const float4*)g_k;
    const bool head_lane = ((lane & 15) == 0);
    const int h = lane >> 4;
    float d = 0.0f;

    if (deg <= EX_CAP) {
        int pos = s0;
        const int qend = s0 + (deg & ~3);
        for (; pos < qend; pos += 4) {
            int2 e0 = g_sedge[pos],     e1 = g_sedge[pos + 1];
            int2 e2 = g_sedge[pos + 2], e3 = g_sedge[pos + 3];
            float4 k0 = __ldg(kp + e0.x * 32 + lane);
            float4 k1 = __ldg(kp + e1.x * 32 + lane);
            float4 k2 = __ldg(kp + e2.x * 32 + lane);
            float4 k3 = __ldg(kp + e3.x * 32 + lane);
            float p0 = qv.x * k0.x + qv.y * k0.y + qv.z * k0.z + qv.w * k0.w;
            float p1 = qv.x * k1.x + qv.y * k1.y + qv.z * k1.z + qv.w * k1.w;
            float p2 = qv.x * k2.x + qv.y * k2.y + qv.z * k2.z + qv.w * k2.w;
            float p3 = qv.x * k3.x + qv.y * k3.y + qv.z * k3.z + qv.w * k3.w;
#pragma unroll
            for (int off = 8; off >= 1; off >>= 1) {
                p0 += __shfl_xor_sync(0xffffffffu, p0, off);
                p1 += __shfl_xor_sync(0xffffffffu, p1, off);
                p2 += __shfl_xor_sync(0xffffffffu, p2, off);
                p3 += __shfl_xor_sync(0xffffffffu, p3, off);
            }
            if (head_lane) {
                int bidx = pos - s0;
                float v0 = __expf(p0), v1 = __expf(p1);
                float v2 = __expf(p2), v3 = __expf(p3);
                ((float*)&exs[warp][bidx + 0])[h] = v0;
                ((float*)&exs[warp][bidx + 1])[h] = v1;
                ((float*)&exs[warp][bidx + 2])[h] = v2;
                ((float*)&exs[warp][bidx + 3])[h] = v3;
                d += (v0 + v1) + (v2 + v3);
            }
        }
        for (; pos < s1; pos++) {
            int2 e0 = g_sedge[pos];
            float4 k0 = __ldg(kp + e0.x * 32 + lane);
            float p0 = qv.x * k0.x + qv.y * k0.y + qv.z * k0.z + qv.w * k0.w;
#pragma unroll
            for (int off = 8; off >= 1; off >>= 1)
                p0 += __shfl_xor_sync(0xffffffffu, p0, off);
            if (head_lane) {
                float v0 = __expf(p0);
                ((float*)&exs[warp][pos - s0])[h] = v0;
                d += v0;
            }
        }
        float D0 = __shfl_sync(0xffffffffu, d, 0);
        float D1 = __shfl_sync(0xffffffffu, d, 16);
        float i0 = 0.5f / D0, i1 = 0.5f / D1;
        __syncwarp();
        for (int j = lane; j < deg; j += 32) {
            float2 e = exs[warp][j];
            out[g_sedge[s0 + j].y] = e.x * i0 + e.y * i1;
        }
    } else {
        for (int pos = s0; pos < s1; pos++) {
            int2 e0 = g_sedge[pos];
            float4 k0 = __ldg(kp + e0.x * 32 + lane);
            float p0 = qv.x * k0.x + qv.y * k0.y + qv.z * k0.z + qv.w * k0.w;
#pragma unroll
            for (int off = 8; off >= 1; off >>= 1)
                p0 += __shfl_xor_sync(0xffffffffu, p0, off);
            if (head_lane) {
                float v0 = __expf(p0);
                g_ex2[2 * (size_t)pos + h] = v0;
                d += v0;
            }
        }
        float D0 = __shfl_sync(0xffffffffu, d, 0);
        float D1 = __shfl_sync(0xffffffffu, d, 16);
        float i0 = 0.5f / D0, i1 = 0.5f / D1;
        __syncwarp();
        for (int j = lane; j < deg; j += 32) {
            float2 e = *(const float2*)(g_ex2 + 2 * (size_t)(s0 + j));
            out[g_sedge[s0 + j].y] = e.x * i0 + e.y * i1;
        }
    }
}

extern "C" void kernel_launch(void* const* d_in, const int* in_sizes, int n_in,
                              void* d_out, int out_size) {
    const float* x    = (const float*)d_in[0];
    const float* W_qk = (const float*)d_in[1];
    const float* b_qk = (const float*)d_in[2];
    const int*   ei   = (const int*)d_in[3];   // [2, E] row-major
    const int* row = ei;
    const int* col = ei + EE;
    float* out = (float*)d_out;

    hist_kernel<<<(EE / 4 + 255) / 256, 256>>>((const int4*)row);
    scan1_kernel<<<SCAN_BLOCKS, 256>>>();
    scan3b_kernel<<<SCAN_BLOCKS, 256>>>();
    scatter_kernel<<<(EE / 4 + 255) / 256, 256>>>((const int4*)row, (const int4*)col);
    gemm_qk_kernel<<<(NN + 63) / 64, 256>>>(x, W_qk, b_qk);
    edge_row_kernel<<<(NN + 7) / 8, 256>>>(out);
}

// round 6
// speedup vs baseline: 1.4139x; 1.0802x over previous
#include <cuda_runtime.h>

#define NN 50000
#define FF 64
#define EE 800000
#define SCAN_BLOCKS ((NN + 255) / 256)   // 196
#define EX_CAP 128

// Scratch (static __device__ — zero-initialized at load; scan1 re-zeros g_hist
// each execution so graph replays are deterministic)
__device__ float g_q[(size_t)NN * 128];      // [N][h*64+f]
__device__ float g_k[(size_t)NN * 128];
__device__ int   g_hist[NN];
__device__ int   g_start[NN + 1];
__device__ int   g_bsum[256];
__device__ int   g_cursor[NN];
__device__ int2  g_sedge[EE];                // (col, orig edge id) row-sorted (compact)
__device__ float g_ex2[(size_t)EE * 2];      // fallback exp storage (deg > EX_CAP)

// f32x2 packed-math helpers (Blackwell FFMA2 path — only reachable via PTX)
#define FMA_F32X2(d, a, b, c) \
    asm("fma.rn.f32x2 %0, %1, %2, %3;" : "=l"(d) : "l"(a), "l"(b), "l"(c))
#define ADD_F32X2(d, a, b) \
    asm("add.rn.f32x2 %0, %1, %2;" : "=l"(d) : "l"(a), "l"(b))
#define PACK_F32X2(d, lo, hi) \
    asm("mov.b64 %0, {%1, %2};" : "=l"(d) : "f"(lo), "f"(hi))
#define UNPACK_F32X2(lo, hi, s) \
    asm("mov.b64 {%0, %1}, %2;" : "=f"(lo), "=f"(hi) : "l"(s))

// ---------------- counting sort of edges by row ----------------

__global__ void hist_kernel(const int4* __restrict__ row4) {
    int i = blockIdx.x * blockDim.x + threadIdx.x;
    if (i < EE / 4) {
        int4 r = __ldg(row4 + i);
        atomicAdd(&g_hist[r.x], 1);
        atomicAdd(&g_hist[r.y], 1);
        atomicAdd(&g_hist[r.z], 1);
        atomicAdd(&g_hist[r.w], 1);
    }
}

// Within-block exclusive scan of hist; also RESETS g_hist for next replay.
__global__ void scan1_kernel() {
    __shared__ int sh[256];
    int t = threadIdx.x;
    int i = blockIdx.x * 256 + t;
    int v = 0;
    if (i < NN) { v = g_hist[i]; g_hist[i] = 0; }
    sh[t] = v;
    __syncthreads();
#pragma unroll
    for (int off = 1; off < 256; off <<= 1) {
        int u = (t >= off) ? sh[t - off] : 0;
        __syncthreads();
        sh[t] += u;
        __syncthreads();
    }
    if (i < NN) g_start[i] = sh[t] - v;
    if (t == 255) g_bsum[blockIdx.x] = sh[t];
}

// Each block tree-reduces its own exclusive prefix over the 196 block sums.
__global__ void scan3b_kernel() {
    __shared__ int sh[256];
    int t = threadIdx.x;
    int bid = blockIdx.x;
    sh[t] = (t < bid && t < SCAN_BLOCKS) ? g_bsum[t] : 0;
    __syncthreads();
#pragma unroll
    for (int off = 128; off >= 1; off >>= 1) {
        if (t < off) sh[t] += sh[t + off];
        __syncthreads();
    }
    int base = sh[0];
    int i = bid * 256 + t;
    if (i < NN) {
        int s = g_start[i] + base;
        g_start[i] = s;
        g_cursor[i] = s;
    }
    if (i == 0) g_start[NN] = EE;
}

__global__ void scatter_kernel(const int* __restrict__ row, const int* __restrict__ col) {
    int e = blockIdx.x * blockDim.x + threadIdx.x;
    if (e >= EE) return;
    int r = row[e];
    int pos = atomicAdd(&g_cursor[r], 1);
    g_sedge[pos] = make_int2(col[e], e);
}

// ---------------- QK projection GEMM (f32x2 / FFMA2) ----------------
__global__ void __launch_bounds__(256, 1) gemm_qk_kernel(const float* __restrict__ x,
                                                         const float* __restrict__ W,
                                                         const float* __restrict__ b) {
    __shared__ float2 xs[64 * 64];   // [row][k] duplicated (v,v) pairs, 32KB
    const int tid = threadIdx.x;
    const int n0 = blockIdx.x * 64;

#pragma unroll
    for (int i = 0; i < 4; i++) {
        int lin = tid + i * 256;          // float4 index
        int r = lin >> 4, k4 = lin & 15;
        int n = n0 + r;
        float4 v = make_float4(0.f, 0.f, 0.f, 0.f);
        if (n < NN) v = __ldg((const float4*)x + (size_t)n * 16 + k4);
        float2* dst = &xs[r * 64 + k4 * 4];
        dst[0] = make_float2(v.x, v.x);
        dst[1] = make_float2(v.y, v.y);
        dst[2] = make_float2(v.z, v.z);
        dst[3] = make_float2(v.w, v.w);
    }

    const int c = tid & 127;              // column pair (c, c+128): two heads
    const int rbase = (tid >> 7) * 32;

    unsigned long long wp[64];
#pragma unroll
    for (int k = 0; k < 64; k++) {
        float w0 = __ldg(W + k * 256 + c);
        float w1 = __ldg(W + k * 256 + c + 128);
        PACK_F32X2(wp[k], w0, w1);
    }
    const float b0 = __ldg(b + c);
    const float b1 = __ldg(b + c + 128);

    __syncthreads();

    const int sflag = (c >> 6) & 1;       // 0 -> q table, 1 -> k table
    const int f = c & 63;
    float* outbase = sflag ? g_k : g_q;

    for (int r = rbase; r < rbase + 32; r++) {
        int n = n0 + r;
        if (n >= NN) break;
        unsigned long long acc_a, acc_b;
        PACK_F32X2(acc_a, b0, b1);
        PACK_F32X2(acc_b, 0.0f, 0.0f);
        const ulonglong2* xr = (const ulonglong2*)&xs[r * 64];
#pragma unroll
        for (int j = 0; j < 32; j++) {
            ulonglong2 xv = xr[j];
            FMA_F32X2(acc_a, xv.x, wp[2 * j], acc_a);
            FMA_F32X2(acc_b, xv.y, wp[2 * j + 1], acc_b);
        }
        unsigned long long acc;
        ADD_F32X2(acc, acc_a, acc_b);
        float o0, o1;
        UNPACK_F32X2(o0, o1, acc);
        outbase[(size_t)n * 128 + f] = o0;
        outbase[(size_t)n * 128 + 64 + f] = o1;
    }
}

// ---------------- fused edge scores + softmax + output (R3-proven) ----------------
__global__ void __launch_bounds__(256) edge_row_kernel(float* __restrict__ out) {
    __shared__ float2 exs[8][EX_CAP + 4];
    const int warp = threadIdx.x >> 5;
    const int lane = threadIdx.x & 31;
    const int r = blockIdx.x * 8 + warp;
    if (r >= NN) return;

    const int s0 = g_start[r];
    const int s1 = g_start[r + 1];
    const int deg = s1 - s0;
    if (deg == 0) return;

    const float4 qv = *(const float4*)(g_q + (size_t)r * 128 + lane * 4);
    const float4* kp = (const float4*)g_k;
    const bool head_lane = ((lane & 15) == 0);
    const int h = lane >> 4;
    float d = 0.0f;

    if (deg <= EX_CAP) {
        int pos = s0;
        const int qend = s0 + (deg & ~3);
        for (; pos < qend; pos += 4) {
            int2 e0 = g_sedge[pos],     e1 = g_sedge[pos + 1];
            int2 e2 = g_sedge[pos + 2], e3 = g_sedge[pos + 3];
            float4 k0 = __ldg(kp + e0.x * 32 + lane);
            float4 k1 = __ldg(kp + e1.x * 32 + lane);
            float4 k2 = __ldg(kp + e2.x * 32 + lane);
            float4 k3 = __ldg(kp + e3.x * 32 + lane);
            float p0 = qv.x * k0.x + qv.y * k0.y + qv.z * k0.z + qv.w * k0.w;
            float p1 = qv.x * k1.x + qv.y * k1.y + qv.z * k1.z + qv.w * k1.w;
            float p2 = qv.x * k2.x + qv.y * k2.y + qv.z * k2.z + qv.w * k2.w;
            float p3 = qv.x * k3.x + qv.y * k3.y + qv.z * k3.z + qv.w * k3.w;
#pragma unroll
            for (int off = 8; off >= 1; off >>= 1) {
                p0 += __shfl_xor_sync(0xffffffffu, p0, off);
                p1 += __shfl_xor_sync(0xffffffffu, p1, off);
                p2 += __shfl_xor_sync(0xffffffffu, p2, off);
                p3 += __shfl_xor_sync(0xffffffffu, p3, off);
            }
            if (head_lane) {
                int bidx = pos - s0;
                float v0 = __expf(p0), v1 = __expf(p1);
                float v2 = __expf(p2), v3 = __expf(p3);
                ((float*)&exs[warp][bidx + 0])[h] = v0;
                ((float*)&exs[warp][bidx + 1])[h] = v1;
                ((float*)&exs[warp][bidx + 2])[h] = v2;
                ((float*)&exs[warp][bidx + 3])[h] = v3;
                d += (v0 + v1) + (v2 + v3);
            }
        }
        for (; pos < s1; pos++) {
            int2 e0 = g_sedge[pos];
            float4 k0 = __ldg(kp + e0.x * 32 + lane);
            float p0 = qv.x * k0.x + qv.y * k0.y + qv.z * k0.z + qv.w * k0.w;
#pragma unroll
            for (int off = 8; off >= 1; off >>= 1)
                p0 += __shfl_xor_sync(0xffffffffu, p0, off);
            if (head_lane) {
                float v0 = __expf(p0);
                ((float*)&exs[warp][pos - s0])[h] = v0;
                d += v0;
            }
        }
        float D0 = __shfl_sync(0xffffffffu, d, 0);
        float D1 = __shfl_sync(0xffffffffu, d, 16);
        float i0 = 0.5f / D0, i1 = 0.5f / D1;
        __syncwarp();
        for (int j = lane; j < deg; j += 32) {
            float2 e = exs[warp][j];
            out[g_sedge[s0 + j].y] = e.x * i0 + e.y * i1;
        }
    } else {
        for (int pos = s0; pos < s1; pos++) {
            int2 e0 = g_sedge[pos];
            float4 k0 = __ldg(kp + e0.x * 32 + lane);
            float p0 = qv.x * k0.x + qv.y * k0.y + qv.z * k0.z + qv.w * k0.w;
#pragma unroll
            for (int off = 8; off >= 1; off >>= 1)
                p0 += __shfl_xor_sync(0xffffffffu, p0, off);
            if (head_lane) {
                float v0 = __expf(p0);
                g_ex2[2 * (size_t)pos + h] = v0;
                d += v0;
            }
        }
        float D0 = __shfl_sync(0xffffffffu, d, 0);
        float D1 = __shfl_sync(0xffffffffu, d, 16);
        float i0 = 0.5f / D0, i1 = 0.5f / D1;
        __syncwarp();
        for (int j = lane; j < deg; j += 32) {
            float2 e = *(const float2*)(g_ex2 + 2 * (size_t)(s0 + j));
            out[g_sedge[s0 + j].y] = e.x * i0 + e.y * i1;
        }
    }
}

extern "C" void kernel_launch(void* const* d_in, const int* in_sizes, int n_in,
                              void* d_out, int out_size) {
    const float* x    = (const float*)d_in[0];
    const float* W_qk = (const float*)d_in[1];
    const float* b_qk = (const float*)d_in[2];
    const int*   ei   = (const int*)d_in[3];   // [2, E] row-major
    const int* row = ei;
    const int* col = ei + EE;
    float* out = (float*)d_out;

    // Fork a parallel branch so the GEMM overlaps the sort pipeline in the
    // captured graph. Stream/events created per call (kernel_launch is only
    // invoked for the correctness run and the capture run; the graph owns the
    // recorded nodes afterward). Not destroyed here: the capture is still in
    // progress when this function returns.
    cudaStream_t s2;
    cudaEvent_t evFork, evJoin;
    cudaStreamCreateWithFlags(&s2, cudaStreamNonBlocking);
    cudaEventCreateWithFlags(&evFork, cudaEventDisableTiming);
    cudaEventCreateWithFlags(&evJoin, cudaEventDisableTiming);

    cudaEventRecord(evFork, 0);
    cudaStreamWaitEvent(s2, evFork, 0);
    gemm_qk_kernel<<<(NN + 63) / 64, 256, 0, s2>>>(x, W_qk, b_qk);
    cudaEventRecord(evJoin, s2);

    hist_kernel<<<(EE / 4 + 255) / 256, 256>>>((const int4*)row);
    scan1_kernel<<<SCAN_BLOCKS, 256>>>();
    scan3b_kernel<<<SCAN_BLOCKS, 256>>>();
    scatter_kernel<<<(EE + 255) / 256, 256>>>(row, col);

    cudaStreamWaitEvent(0, evJoin, 0);
    edge_row_kernel<<<(NN + 7) / 8, 256>>>(out);
}